// round 7
// baseline (speedup 1.0000x reference)
#include <cuda_runtime.h>
#include <stdint.h>

// ============================================================================
// Problem constants (fixed per reference source)
// ============================================================================
#define K_DIM 4096
#define N_DIM 4096
#define M_MAX 8192
#define HASH_MASK 0xFFFFF        // HASH_SIZE = 2^20
#define P_CONST 56598313LL       // RzLinear.P (prime), hardcoded in reference

// Scratch (device globals; no allocation allowed)
// g_A: [M][K] tf32, per-8 interleave: out[2*lr+j] = in[lr+4*j]  (pairs k,k+4)
// g_B: [K/32][16][N][2] tf32 pair-major: word ((kb*16+kp)*N + n)*2 + j
//      kp = (k%4) + 4*((k%32)/8),  j = (k%8)/4
__device__ uint32_t g_A[(size_t)M_MAX * K_DIM];
__device__ uint32_t g_B[(size_t)K_DIM * N_DIM];
__device__ int      g_rowmod[K_DIM];              // (k*r3 + r1) % P
__device__ int      g_colmod[N_DIM];              // (n*r2) % P

__device__ __forceinline__ uint32_t f32_to_tf32_rn(float f) {
    uint32_t u;
    asm("cvt.rna.tf32.f32 %0, %1;" : "=r"(u) : "f"(f));
    return u;
}
__device__ __forceinline__ uint32_t smem_u32(const void* p) {
    uint32_t a;
    asm("{ .reg .u64 t; cvta.to.shared.u64 t, %1; cvt.u32.u64 %0, t; }"
        : "=r"(a) : "l"(p));
    return a;
}
__device__ __forceinline__ void cp_async16(uint32_t dst, const void* src) {
    asm volatile("cp.async.cg.shared.global [%0], [%1], 16;"
                 :: "r"(dst), "l"(src) : "memory");
}
#define CP_COMMIT() asm volatile("cp.async.commit_group;" ::: "memory")
#define CP_WAIT2()  asm volatile("cp.async.wait_group 2;"  ::: "memory")
#define CP_WAIT0()  asm volatile("cp.async.wait_group 0;"  ::: "memory")

// m16n8k8 tf32 MMA (generic PTX, sm_80+; runs on the tensor pipe)
__device__ __forceinline__ void mma_tf32(float c[4], uint32_t a0, uint32_t a1,
                                         uint32_t a2, uint32_t a3,
                                         uint32_t b0, uint32_t b1) {
    asm volatile(
        "mma.sync.aligned.m16n8k8.row.col.f32.tf32.tf32.f32 "
        "{%0,%1,%2,%3}, {%4,%5,%6,%7}, {%8,%9}, {%0,%1,%2,%3};"
        : "+f"(c[0]), "+f"(c[1]), "+f"(c[2]), "+f"(c[3])
        : "r"(a0), "r"(a1), "r"(a2), "r"(a3), "r"(b0), "r"(b1));
}

// ============================================================================
// Kernel 1: hash residue tables (self-detects int64 vs int32 materialization)
// ============================================================================
__global__ void hash_tables_kernel(const void* __restrict__ rn_raw) {
    const long long* rn64 = (const long long*)rn_raw;
    const int*       rn32 = (const int*)rn_raw;
    long long r1, r2, r3;
    if (rn64[0] == P_CONST) { r1 = rn64[1]; r2 = rn64[2]; r3 = rn64[3]; }
    else                    { r1 = rn32[1]; r2 = rn32[2]; r3 = rn32[3]; }
    int i = blockIdx.x * blockDim.x + threadIdx.x;
    if (i < K_DIM) g_rowmod[i] = (int)(((long long)i * r3 + r1) % P_CONST);
    if (i < N_DIM) g_colmod[i] = (int)(((long long)i * r2) % P_CONST);
}

// ============================================================================
// Kernel 2: gather W into pair-major tf32 layout
//   thread t -> one uint4 = { (k0,n), (k1,n), (k0,n+1), (k1,n+1) }
//   where t = (kb*16 + kp)*(N/2) + n/2,  k0 = kb*32 + (kp>>2)*8 + (kp&3),
//   k1 = k0 + 4. Fully coalesced 16B writes.
// ============================================================================
__global__ void gather_kernel(const float* __restrict__ hw) {
    const int P = (int)P_CONST;
    const int t = blockIdx.x * blockDim.x + threadIdx.x;
    const int total = (K_DIM / 32) * 16 * (N_DIM / 2);
    if (t >= total) return;

    const int n2  = t & (N_DIM / 2 - 1);
    const int row = t >> 11;            // (kb*16 + kp)
    const int kp  = row & 15;
    const int kb  = row >> 4;
    const int k0  = kb * 32 + (kp >> 2) * 8 + (kp & 3);
    const int n   = n2 * 2;

    const int rm0 = g_rowmod[k0];
    const int rm1 = g_rowmod[k0 + 4];
    const int c0  = g_colmod[n];
    const int c1  = g_colmod[n + 1];

    int s00 = rm0 + c0; if (s00 >= P) s00 -= P;
    int s10 = rm1 + c0; if (s10 >= P) s10 -= P;
    int s01 = rm0 + c1; if (s01 >= P) s01 -= P;
    int s11 = rm1 + c1; if (s11 >= P) s11 -= P;

    uint4 w;
    w.x = f32_to_tf32_rn(__ldg(hw + (s00 & HASH_MASK)));
    w.y = f32_to_tf32_rn(__ldg(hw + (s10 & HASH_MASK)));
    w.z = f32_to_tf32_rn(__ldg(hw + (s01 & HASH_MASK)));
    w.w = f32_to_tf32_rn(__ldg(hw + (s11 & HASH_MASK)));

    ((uint4*)g_B)[t] = w;
}

// ============================================================================
// Kernel 3: x -> tf32 with per-8 (k, k+4) pair interleave
//   out8 = [in0,in4,in1,in5,in2,in6,in3,in7]
// ============================================================================
__global__ void cvt_a_kernel(const float* __restrict__ x, int total8) {
    int t = blockIdx.x * blockDim.x + threadIdx.x;
    if (t >= total8) return;
    float4 v0 = ((const float4*)x)[2 * t];
    float4 v1 = ((const float4*)x)[2 * t + 1];
    uint4 o0, o1;
    o0.x = f32_to_tf32_rn(v0.x); o0.y = f32_to_tf32_rn(v1.x);
    o0.z = f32_to_tf32_rn(v0.y); o0.w = f32_to_tf32_rn(v1.y);
    o1.x = f32_to_tf32_rn(v0.z); o1.y = f32_to_tf32_rn(v1.z);
    o1.z = f32_to_tf32_rn(v0.w); o1.w = f32_to_tf32_rn(v1.w);
    ((uint4*)g_A)[2 * t]     = o0;
    ((uint4*)g_A)[2 * t + 1] = o1;
}

// ============================================================================
// Kernel 4: tf32 tensor-core GEMM via mma.sync
//   CTA tile 128x256, BK=32, 256 thr (8 warps 2x4 -> warp tile 64x64),
//   4-stage cp.async pipeline + explicit per-k8 fragment double-buffering:
//   fragments for step kk+1 are LDS'd while the 32-MMA burst of step kk runs,
//   so the 29-cyc LDS latency is covered inside a single warp.
// SMEM strides ≡ 8 (mod 32) words -> conflict-free 64-bit accesses:
//   As: [128 rows m][40 words]   (32 data words, per-8 pair-interleaved)
//   Bs: [16 rows kp][520 words]  (512 data words = 256 n-pairs)
// ============================================================================
#define SA_W 40
#define SB_W 520
#define A_STAGE_B (128 * SA_W * 4)                 // 20480
#define B_STAGE_B (16 * SB_W * 4)                  // 33280
#define STAGE_B   (A_STAGE_B + B_STAGE_B)          // 53760
#define NSTAGE 4
#define SMEM_GEMM (NSTAGE * STAGE_B)               // 215040
#define NK        (K_DIM / 32)                     // 128

__device__ __forceinline__ void load_stage(uint32_t sbase, int stage,
                                           int m0, int n0, int kt, int tid) {
    const uint32_t a_s = sbase + stage * STAGE_B;
    const uint32_t b_s = a_s + A_STAGE_B;
    // A: 128 rows x 32 words; 8 chunks/row, 2 threads/row (4 chunks each)
    {
        const int row = tid >> 1;
        const int cb  = (tid & 1) * 4;
        const uint32_t* src = g_A + (size_t)(m0 + row) * K_DIM + kt * 32 + cb * 4;
        const uint32_t dst = a_s + row * (SA_W * 4) + cb * 16;
        #pragma unroll
        for (int j = 0; j < 4; j++)
            cp_async16(dst + j * 16, src + j * 4);
    }
    // B: 16 rows (kp) x 512 words; 128 chunks/row, 16 threads/row (8 each)
    {
        const int r = tid >> 4;
        const int c = tid & 15;
        const uint32_t* src =
            g_B + ((size_t)(kt * 16 + r) * N_DIM + n0) * 2 + c * 4;
        const uint32_t dst = b_s + r * (SB_W * 4) + c * 16;
        #pragma unroll
        for (int j = 0; j < 8; j++)
            cp_async16(dst + j * 256, src + j * 64);
    }
}

__global__ __launch_bounds__(256, 1)
void gemm_mma_kernel(const float* __restrict__ bias, float* __restrict__ C) {
    extern __shared__ char smem[];
    const uint32_t sbase = smem_u32(smem);
    const int tid  = threadIdx.x;
    const int wid  = tid >> 5;
    const int lane = tid & 31;
    const int lq = lane >> 2;     // 0..7
    const int lr = lane & 3;      // 0..3
    const int wm = wid & 1;       // 2 m-halves of 64
    const int wn = wid >> 1;      // 4 n-quarters of 64

    const int m_blk = blockIdx.y * 128;
    const int n_blk = blockIdx.x * 256;

    float acc[4][8][4];
    #pragma unroll
    for (int i = 0; i < 4; i++)
        #pragma unroll
        for (int j = 0; j < 8; j++)
            #pragma unroll
            for (int r = 0; r < 4; r++) acc[i][j][r] = 0.0f;

    load_stage(sbase, 0, m_blk, n_blk, 0, tid); CP_COMMIT();
    load_stage(sbase, 1, m_blk, n_blk, 1, tid); CP_COMMIT();
    load_stage(sbase, 2, m_blk, n_blk, 2, tid); CP_COMMIT();

    // fragment double buffers
    uint2 a_lo[2][4], a_hi[2][4], b[2][8];

    int st = 0;
    for (int kt = 0; kt < NK; kt++) {
        CP_WAIT2();
        __syncthreads();

        const uint32_t* As = (const uint32_t*)(smem + st * STAGE_B);
        const uint32_t* Bs = (const uint32_t*)(smem + st * STAGE_B + A_STAGE_B);

        // prefetch fragments for k8-step 0
        {
            const int kpo = lr * 2;
            #pragma unroll
            for (int im = 0; im < 4; im++) {
                const uint32_t* ap = As + (wm * 64 + im * 16 + lq) * SA_W + kpo;
                a_lo[0][im] = *(const uint2*)ap;
                a_hi[0][im] = *(const uint2*)(ap + 8 * SA_W);
            }
            #pragma unroll
            for (int jn = 0; jn < 8; jn++)
                b[0][jn] = *(const uint2*)
                    (Bs + lr * SB_W + (wn * 64 + jn * 8 + lq) * 2);
        }

        #pragma unroll
        for (int kk = 0; kk < 4; kk++) {
            const int cb = kk & 1;
            const int nb = cb ^ 1;
            if (kk < 3) {   // prefetch next k8-step while this burst runs
                const int kpo = (lr + 4 * (kk + 1)) * 2;
                #pragma unroll
                for (int im = 0; im < 4; im++) {
                    const uint32_t* ap =
                        As + (wm * 64 + im * 16 + lq) * SA_W + kpo;
                    a_lo[nb][im] = *(const uint2*)ap;
                    a_hi[nb][im] = *(const uint2*)(ap + 8 * SA_W);
                }
                #pragma unroll
                for (int jn = 0; jn < 8; jn++)
                    b[nb][jn] = *(const uint2*)
                        (Bs + (lr + 4 * (kk + 1)) * SB_W +
                         (wn * 64 + jn * 8 + lq) * 2);
            }
            #pragma unroll
            for (int im = 0; im < 4; im++)
                #pragma unroll
                for (int jn = 0; jn < 8; jn++)
                    mma_tf32(acc[im][jn],
                             a_lo[cb][im].x, a_hi[cb][im].x,
                             a_lo[cb][im].y, a_hi[cb][im].y,
                             b[cb][jn].x, b[cb][jn].y);
        }

        __syncthreads();
        if (kt + 3 < NK)
            load_stage(sbase, (st + 3) & (NSTAGE - 1), m_blk, n_blk, kt + 3, tid);
        CP_COMMIT();   // keep group count in lockstep even when empty
        st = (st + 1) & (NSTAGE - 1);
    }
    CP_WAIT0();

    // epilogue: bias + direct stores
    #pragma unroll
    for (int jn = 0; jn < 8; jn++) {
        const int c0 = n_blk + wn * 64 + jn * 8 + 2 * lr;
        const float bx = __ldg(bias + c0);
        const float by = __ldg(bias + c0 + 1);
        #pragma unroll
        for (int im = 0; im < 4; im++) {
            const int r0 = m_blk + wm * 64 + im * 16 + lq;
            float2 v0, v1;
            v0.x = acc[im][jn][0] + bx; v0.y = acc[im][jn][1] + by;
            v1.x = acc[im][jn][2] + bx; v1.y = acc[im][jn][3] + by;
            *(float2*)(C + (size_t)r0 * N_DIM + c0)       = v0;
            *(float2*)(C + (size_t)(r0 + 8) * N_DIM + c0) = v1;
        }
    }
}

// ============================================================================
// Host launch. Inputs routed by element count (immune to metadata ordering):
//   <=8 elems -> random_numbers; 2^20 -> hashed_weight; 4096 -> bias;
//   largest -> x. Output f32 [M, N_DIM].
// ============================================================================
extern "C" void kernel_launch(void* const* d_in, const int* in_sizes, int n_in,
                              void* d_out, int out_size) {
    const float* x = nullptr; const float* hw = nullptr;
    const void* rn = nullptr; const float* bias = nullptr;
    long long max_sz = -1; int max_i = 0;
    for (int i = 0; i < n_in; i++)
        if ((long long)in_sizes[i] > max_sz) { max_sz = in_sizes[i]; max_i = i; }
    x = (const float*)d_in[max_i];
    for (int i = 0; i < n_in; i++) {
        if (i == max_i) continue;
        if (in_sizes[i] <= 8)              rn   = d_in[i];
        else if (in_sizes[i] == (1 << 20)) hw   = (const float*)d_in[i];
        else if (in_sizes[i] == N_DIM)     bias = (const float*)d_in[i];
    }
    float* out = (float*)d_out;
    const int M = (int)(max_sz / K_DIM);   // 8192

    hash_tables_kernel<<<(K_DIM + 255) / 256, 256>>>(rn);

    const int total8 = M * K_DIM / 8;
    cvt_a_kernel<<<(total8 + 255) / 256, 256>>>(x, total8);

    const int gthreads = (K_DIM / 32) * 16 * (N_DIM / 2);
    gather_kernel<<<(gthreads + 255) / 256, 256>>>(hw);

    static bool smem_set = false;
    if (!smem_set) {
        cudaFuncSetAttribute(gemm_mma_kernel,
                             cudaFuncAttributeMaxDynamicSharedMemorySize,
                             SMEM_GEMM);
        smem_set = true;
    }
    dim3 grid(N_DIM / 256, M / 128);
    gemm_mma_kernel<<<grid, 256, SMEM_GEMM>>>(bias, out);
}

// round 8
// speedup vs baseline: 1.3788x; 1.3788x over previous
#include <cuda_runtime.h>
#include <stdint.h>

// ============================================================================
// Problem constants (fixed per reference source)
// ============================================================================
#define K_DIM 4096
#define N_DIM 4096
#define M_MAX 8192
#define HASH_MASK 0xFFFFF        // HASH_SIZE = 2^20
#define P_CONST 56598313LL       // RzLinear.P (prime), hardcoded in reference

// Scratch (device globals; no allocation allowed)
// g_A: fragment-major tf32: [M/16][K/8][32 lanes][4 words]; the 4 words of
//      entry (mt,k8,lane) are the thread's m16n8k8 A-fragment {a0,a1,a2,a3}:
//      a0=(m=lq,k=lr) a1=(lq+8,lr) a2=(lq,lr+4) a3=(lq+8,lr+4), lane=lq*4+lr.
// g_B: [K/32][16][N][2] tf32 pair-major: word ((kb*16+kp)*N + n)*2 + j
//      kp = (k%4) + 4*((k%32)/8),  j = (k%8)/4
__device__ uint32_t g_A[(size_t)M_MAX * K_DIM];
__device__ uint32_t g_B[(size_t)K_DIM * N_DIM];
__device__ int      g_rowmod[K_DIM];              // (k*r3 + r1) % P
__device__ int      g_colmod[N_DIM];              // (n*r2) % P

__device__ __forceinline__ uint32_t f32_to_tf32_rn(float f) {
    uint32_t u;
    asm("cvt.rna.tf32.f32 %0, %1;" : "=r"(u) : "f"(f));
    return u;
}
__device__ __forceinline__ uint32_t smem_u32(const void* p) {
    uint32_t a;
    asm("{ .reg .u64 t; cvta.to.shared.u64 t, %1; cvt.u32.u64 %0, t; }"
        : "=r"(a) : "l"(p));
    return a;
}
__device__ __forceinline__ void cp_async16(uint32_t dst, const void* src) {
    asm volatile("cp.async.cg.shared.global [%0], [%1], 16;"
                 :: "r"(dst), "l"(src) : "memory");
}
#define CP_COMMIT() asm volatile("cp.async.commit_group;" ::: "memory")
#define CP_WAIT2()  asm volatile("cp.async.wait_group 2;"  ::: "memory")
#define CP_WAIT0()  asm volatile("cp.async.wait_group 0;"  ::: "memory")

// m16n8k8 tf32 MMA (generic PTX, sm_80+; runs on the tensor pipe)
__device__ __forceinline__ void mma_tf32(float c[4], uint32_t a0, uint32_t a1,
                                         uint32_t a2, uint32_t a3,
                                         uint32_t b0, uint32_t b1) {
    asm volatile(
        "mma.sync.aligned.m16n8k8.row.col.f32.tf32.tf32.f32 "
        "{%0,%1,%2,%3}, {%4,%5,%6,%7}, {%8,%9}, {%0,%1,%2,%3};"
        : "+f"(c[0]), "+f"(c[1]), "+f"(c[2]), "+f"(c[3])
        : "r"(a0), "r"(a1), "r"(a2), "r"(a3), "r"(b0), "r"(b1));
}

// ============================================================================
// Kernel 1: hash residue tables (self-detects int64 vs int32 materialization)
// ============================================================================
__global__ void hash_tables_kernel(const void* __restrict__ rn_raw) {
    const long long* rn64 = (const long long*)rn_raw;
    const int*       rn32 = (const int*)rn_raw;
    long long r1, r2, r3;
    if (rn64[0] == P_CONST) { r1 = rn64[1]; r2 = rn64[2]; r3 = rn64[3]; }
    else                    { r1 = rn32[1]; r2 = rn32[2]; r3 = rn32[3]; }
    int i = blockIdx.x * blockDim.x + threadIdx.x;
    if (i < K_DIM) g_rowmod[i] = (int)(((long long)i * r3 + r1) % P_CONST);
    if (i < N_DIM) g_colmod[i] = (int)(((long long)i * r2) % P_CONST);
}

// ============================================================================
// Kernel 2: gather W into pair-major tf32 layout (unchanged from R6)
// ============================================================================
__global__ void gather_kernel(const float* __restrict__ hw) {
    const int P = (int)P_CONST;
    const int t = blockIdx.x * blockDim.x + threadIdx.x;
    const int total = (K_DIM / 32) * 16 * (N_DIM / 2);
    if (t >= total) return;

    const int n2  = t & (N_DIM / 2 - 1);
    const int row = t >> 11;            // (kb*16 + kp)
    const int kp  = row & 15;
    const int kb  = row >> 4;
    const int k0  = kb * 32 + (kp >> 2) * 8 + (kp & 3);
    const int n   = n2 * 2;

    const int rm0 = g_rowmod[k0];
    const int rm1 = g_rowmod[k0 + 4];
    const int c0  = g_colmod[n];
    const int c1  = g_colmod[n + 1];

    int s00 = rm0 + c0; if (s00 >= P) s00 -= P;
    int s10 = rm1 + c0; if (s10 >= P) s10 -= P;
    int s01 = rm0 + c1; if (s01 >= P) s01 -= P;
    int s11 = rm1 + c1; if (s11 >= P) s11 -= P;

    uint4 w;
    w.x = f32_to_tf32_rn(__ldg(hw + (s00 & HASH_MASK)));
    w.y = f32_to_tf32_rn(__ldg(hw + (s10 & HASH_MASK)));
    w.z = f32_to_tf32_rn(__ldg(hw + (s01 & HASH_MASK)));
    w.w = f32_to_tf32_rn(__ldg(hw + (s11 & HASH_MASK)));

    ((uint4*)g_B)[t] = w;
}

// ============================================================================
// Kernel 3: x -> tf32, fragment-major permutation
//   thread t = (mt*(K/8) + k8)*32 + lane; writes one 16B fragment entry.
// ============================================================================
__global__ void cvt_a_kernel(const float* __restrict__ x, int total) {
    int t = blockIdx.x * blockDim.x + threadIdx.x;
    if (t >= total) return;
    const int lane = t & 31;
    const int k8   = (t >> 5) & (K_DIM / 8 - 1);
    const int mt   = t >> (5 + 9);            // K/8 = 512 -> 9 bits
    const int lq = lane >> 2, lr = lane & 3;
    const float* xm = x + (size_t)(mt * 16) * K_DIM + k8 * 8;
    uint4 o;
    o.x = f32_to_tf32_rn(__ldg(xm + (size_t)lq * K_DIM + lr));
    o.y = f32_to_tf32_rn(__ldg(xm + (size_t)(lq + 8) * K_DIM + lr));
    o.z = f32_to_tf32_rn(__ldg(xm + (size_t)lq * K_DIM + lr + 4));
    o.w = f32_to_tf32_rn(__ldg(xm + (size_t)(lq + 8) * K_DIM + lr + 4));
    ((uint4*)g_A)[t] = o;
}

// ============================================================================
// Kernel 4: tf32 tensor-core GEMM via mma.sync
//   CTA tile 128x256, BK=32, 512 thr (16 warps 2x8 -> warp tile 64x32),
//   4-stage cp.async pipeline, ONE __syncthreads per kt.
//   A fragments: 1x LDS.128 each (fragment-major smem, zero padding,
//   consecutive lanes -> consecutive 16B, conflict-free).
//   B fragments: 1x LDS.64 each (pair-major, SB_W=520 ≡ 8 mod 32).
// ============================================================================
#define SB_W 520
#define A_STAGE_B (128 * 32 * 4)                   // 16384, frag-major
#define B_STAGE_B (16 * SB_W * 4)                  // 33280
#define STAGE_B   (A_STAGE_B + B_STAGE_B)          // 49664
#define NSTAGE 4
#define SMEM_GEMM (NSTAGE * STAGE_B)               // 198656
#define NK        (K_DIM / 32)                     // 128

__device__ __forceinline__ void load_stage(uint32_t sbase, int stage,
                                           int m0, int n0, int kt, int tid) {
    const uint32_t a_s = sbase + stage * STAGE_B;
    const uint32_t b_s = a_s + A_STAGE_B;
    // A: 32 fragment-chunks of 512B (i = mtile 0..7, j = kk 0..3);
    //    1024 x 16B transfers, 2 per thread, gmem chunk = contiguous 512B.
    {
        #pragma unroll
        for (int p = 0; p < 2; p++) {
            const int u     = tid + p * 512;
            const int chunk = u >> 5;            // 0..31
            const int lane  = u & 31;
            const int i = chunk >> 2;            // mtile within CTA
            const int j = chunk & 3;             // kk
            const uint32_t* src = g_A +
                (((size_t)(m0 / 16 + i) * (K_DIM / 8) + (kt * 4 + j)) * 32
                 + lane) * 4;
            cp_async16(a_s + u * 16, src);
        }
    }
    // B: 16 rows (kp) x 512 words; 128 chunks/row, 32 threads/row, 4 each
    {
        const int r = tid >> 5;
        const int c = tid & 31;
        const uint32_t* src =
            g_B + ((size_t)(kt * 16 + r) * N_DIM + n0) * 2 + c * 4;
        const uint32_t dst = b_s + r * (SB_W * 4) + c * 16;
        #pragma unroll
        for (int j = 0; j < 4; j++)
            cp_async16(dst + j * 512, src + j * 128);
    }
}

__global__ __launch_bounds__(512, 1)
void gemm_mma_kernel(const float* __restrict__ bias, float* __restrict__ C) {
    extern __shared__ char smem[];
    const uint32_t sbase = smem_u32(smem);
    const int tid  = threadIdx.x;
    const int wid  = tid >> 5;
    const int lane = tid & 31;
    const int lq = lane >> 2;     // 0..7
    const int lr = lane & 3;      // 0..3
    const int wm = wid & 1;       // 2 m-halves of 64
    const int wn = wid >> 1;      // 8 n-slices of 32

    const int m_blk = blockIdx.y * 128;
    const int n_blk = blockIdx.x * 256;

    float acc[4][4][4];
    #pragma unroll
    for (int i = 0; i < 4; i++)
        #pragma unroll
        for (int j = 0; j < 4; j++)
            #pragma unroll
            for (int r = 0; r < 4; r++) acc[i][j][r] = 0.0f;

    load_stage(sbase, 0, m_blk, n_blk, 0, tid); CP_COMMIT();
    load_stage(sbase, 1, m_blk, n_blk, 1, tid); CP_COMMIT();
    load_stage(sbase, 2, m_blk, n_blk, 2, tid); CP_COMMIT();

    for (int kt = 0; kt < NK; kt++) {
        CP_WAIT2();
        __syncthreads();    // the ONLY barrier per kt (NSTAGE=4 makes the
                            // written slot (kt-1)&3, already drained here)
        const int st = kt & (NSTAGE - 1);
        const uint32_t* As = (const uint32_t*)(smem + st * STAGE_B);
        const uint32_t* Bs = (const uint32_t*)(smem + st * STAGE_B + A_STAGE_B);

        // hoisted per-warp bases
        const uint32_t* a_base = As + ((wm * 4) * 4) * 128 + lane * 4;
        const uint32_t* b_base = Bs + lr * SB_W + (wn * 32 + lq) * 2;

        #pragma unroll
        for (int kk = 0; kk < 4; kk++) {
            uint4 a[4];
            #pragma unroll
            for (int im = 0; im < 4; im++)
                a[im] = *(const uint4*)(a_base + (im * 4 + kk) * 128);
            uint2 b[4];
            #pragma unroll
            for (int jn = 0; jn < 4; jn++)
                b[jn] = *(const uint2*)(b_base + 4 * kk * SB_W + jn * 16);
            #pragma unroll
            for (int im = 0; im < 4; im++)
                #pragma unroll
                for (int jn = 0; jn < 4; jn++)
                    mma_tf32(acc[im][jn], a[im].x, a[im].y, a[im].z, a[im].w,
                             b[jn].x, b[jn].y);
        }

        if (kt + 3 < NK)
            load_stage(sbase, (kt + 3) & (NSTAGE - 1), m_blk, n_blk,
                       kt + 3, tid);
        CP_COMMIT();   // keep group count in lockstep even when empty
    }
    CP_WAIT0();

    // epilogue: bias + direct stores
    #pragma unroll
    for (int jn = 0; jn < 4; jn++) {
        const int c0 = n_blk + wn * 32 + jn * 8 + 2 * lr;
        const float bx = __ldg(bias + c0);
        const float by = __ldg(bias + c0 + 1);
        #pragma unroll
        for (int im = 0; im < 4; im++) {
            const int r0 = m_blk + wm * 64 + im * 16 + lq;
            float2 v0, v1;
            v0.x = acc[im][jn][0] + bx; v0.y = acc[im][jn][1] + by;
            v1.x = acc[im][jn][2] + bx; v1.y = acc[im][jn][3] + by;
            *(float2*)(C + (size_t)r0 * N_DIM + c0)       = v0;
            *(float2*)(C + (size_t)(r0 + 8) * N_DIM + c0) = v1;
        }
    }
}

// ============================================================================
// Host launch. Inputs routed by element count (immune to metadata ordering):
//   <=8 elems -> random_numbers; 2^20 -> hashed_weight; 4096 -> bias;
//   largest -> x. Output f32 [M, N_DIM].
// ============================================================================
extern "C" void kernel_launch(void* const* d_in, const int* in_sizes, int n_in,
                              void* d_out, int out_size) {
    const float* x = nullptr; const float* hw = nullptr;
    const void* rn = nullptr; const float* bias = nullptr;
    long long max_sz = -1; int max_i = 0;
    for (int i = 0; i < n_in; i++)
        if ((long long)in_sizes[i] > max_sz) { max_sz = in_sizes[i]; max_i = i; }
    x = (const float*)d_in[max_i];
    for (int i = 0; i < n_in; i++) {
        if (i == max_i) continue;
        if (in_sizes[i] <= 8)              rn   = d_in[i];
        else if (in_sizes[i] == (1 << 20)) hw   = (const float*)d_in[i];
        else if (in_sizes[i] == N_DIM)     bias = (const float*)d_in[i];
    }
    float* out = (float*)d_out;
    const int M = (int)(max_sz / K_DIM);   // 8192

    hash_tables_kernel<<<(K_DIM + 255) / 256, 256>>>(rn);

    const int a_total = (M / 16) * (K_DIM / 8) * 32;
    cvt_a_kernel<<<(a_total + 255) / 256, 256>>>(x, a_total);

    const int gthreads = (K_DIM / 32) * 16 * (N_DIM / 2);
    gather_kernel<<<(gthreads + 255) / 256, 256>>>(hw);

    static bool smem_set = false;
    if (!smem_set) {
        cudaFuncSetAttribute(gemm_mma_kernel,
                             cudaFuncAttributeMaxDynamicSharedMemorySize,
                             SMEM_GEMM);
        smem_set = true;
    }
    dim3 grid(N_DIM / 256, M / 128);
    gemm_mma_kernel<<<grid, 512, SMEM_GEMM>>>(bias, out);
}